// round 16
// baseline (speedup 1.0000x reference)
#include <cuda_runtime.h>
#include <cstdint>
#include <cstddef>

// Problem constants
#define BB     2
#define SEQ    4096
#define DMODEL 512
#define NHEADS 8
#define DH     64
#define MTOT   (BB * SEQ)
#define BHTOT  (BB * NHEADS)
#define NBLK   (SEQ / 128)          // 32 n-blocks per row (scores tile = 128)
#define HGRP   4                    // heads per pipeline group
#define NGRP   (BHTOT / HGRP)       // 4 groups

// Scratch device globals (no allocation allowed)
__device__ float g_Q[MTOT * DMODEL];
__device__ float g_K[MTOT * DMODEL];
__device__ float g_V[MTOT * DMODEL];
__device__ float g_C[MTOT * DMODEL];
__device__ float g_ps[NBLK * BHTOT * SEQ];   // rowsum partials [nblk][bh*SEQ+row]

// ---------------------------------------------------------------------------
// tf32 / async helpers (base ISA, no sm_103a-gated features)
// ---------------------------------------------------------------------------
__device__ __forceinline__ uint32_t cvt_tf32(float f) {
    uint32_t u;
    asm("cvt.rna.tf32.f32 %0, %1;" : "=r"(u) : "f"(f));
    return u;
}

__device__ __forceinline__ uint4 tf32x4(float4 v) {
    uint4 u;
    u.x = cvt_tf32(v.x); u.y = cvt_tf32(v.y);
    u.z = cvt_tf32(v.z); u.w = cvt_tf32(v.w);
    return u;
}

__device__ __forceinline__ uint32_t smem_u32(const void* p) {
    uint32_t a;
    asm("{ .reg .u64 t; cvta.to.shared.u64 t, %1; cvt.u32.u64 %0, t; }"
        : "=r"(a) : "l"(p));
    return a;
}

#define CP_ASYNC16(dst_u32, src_ptr) \
    asm volatile("cp.async.cg.shared.global [%0], [%1], 16;" \
        :: "r"(dst_u32), "l"(src_ptr) : "memory")
#define CP_COMMIT() asm volatile("cp.async.commit_group;" ::: "memory")
#define CP_WAIT2()  asm volatile("cp.async.wait_group 2;" ::: "memory")

// D = A(16x8, row) * B(8x8, col) + C, tf32 in / fp32 out. In-place C allowed.
__device__ __forceinline__ void mma_tf32(
    float d[4], const uint32_t a[4], const uint32_t b[2])
{
    asm volatile(
        "mma.sync.aligned.m16n8k8.row.col.f32.tf32.tf32.f32 "
        "{%0,%1,%2,%3}, {%4,%5,%6,%7}, {%8,%9}, {%0,%1,%2,%3};\n"
        : "+f"(d[0]), "+f"(d[1]), "+f"(d[2]), "+f"(d[3])
        : "r"(a[0]), "r"(a[1]), "r"(a[2]), "r"(a[3]),
          "r"(b[0]), "r"(b[1]));
}

// ---------------------------------------------------------------------------
// Core projection body (R12-proven 64x32 warp tile): Y = X @ W^T + b
// CTA 128x128, 8 warps 2x4, warp 64x32, K = 512 in 8 staged chunks.
// Dyn smem: Xs 128x68 u32 @0, Ws 128x68 u32 @34816 -> 69632 bytes.
// ---------------------------------------------------------------------------
__device__ __forceinline__ void proj_body(
    const float* __restrict__ X, const float* __restrict__ W,
    const float* __restrict__ bias, float* __restrict__ Y, char* smem)
{
    uint32_t* Xs = (uint32_t*)smem;               // stride 68 words
    uint32_t* Ws = (uint32_t*)(smem + 34816);

    const int tid = threadIdx.x;
    const int wid = tid >> 5, lid = tid & 31;
    const int g = lid >> 2, tig = lid & 3;
    const int wm = wid >> 2, wn = wid & 3;        // 2 x 4 warp grid
    const int m0 = blockIdx.y * 128, n0 = blockIdx.x * 128;

    float acc[4][4][4] = {};                      // [mi][ni][frag]

    for (int kc = 0; kc < DMODEL / 64; kc++) {
        const int kb = kc * 64;
#pragma unroll
        for (int i = 0; i < 8; i++) {
            int idx = tid + i * 256;              // 0..2047
            int r = idx >> 4, c4 = idx & 15;      // 16 float4 per 64-col row
            float4 x = *(const float4*)&X[(size_t)(m0 + r) * DMODEL + kb + c4 * 4];
            *(uint4*)(Xs + r * 68 + c4 * 4) = tf32x4(x);
            float4 w = *(const float4*)&W[(size_t)(n0 + r) * DMODEL + kb + c4 * 4];
            *(uint4*)(Ws + r * 68 + c4 * 4) = tf32x4(w);
        }
        __syncthreads();
#pragma unroll
        for (int ks = 0; ks < 8; ks++) {
            const int k0 = ks * 8;
            uint32_t A[4][4], Bf[4][2];
#pragma unroll
            for (int mi = 0; mi < 4; mi++) {
                const uint32_t* p = Xs + (wm * 64 + mi * 16 + g) * 68 + k0 + tig;
                A[mi][0] = p[0];
                A[mi][1] = p[8 * 68];
                A[mi][2] = p[4];
                A[mi][3] = p[8 * 68 + 4];
            }
#pragma unroll
            for (int ni = 0; ni < 4; ni++) {
                const uint32_t* p = Ws + (wn * 32 + ni * 8 + g) * 68 + k0 + tig;
                Bf[ni][0] = p[0];
                Bf[ni][1] = p[4];
            }
#pragma unroll
            for (int mi = 0; mi < 4; mi++)
#pragma unroll
                for (int ni = 0; ni < 4; ni++)
                    mma_tf32(acc[mi][ni], A[mi], Bf[ni]);
        }
        __syncthreads();
    }

    // Epilogue: bias add, float2 stores
#pragma unroll
    for (int mi = 0; mi < 4; mi++) {
#pragma unroll
        for (int half = 0; half < 2; half++) {
            int rl = wm * 64 + mi * 16 + g + half * 8;
            size_t rbase = (size_t)(m0 + rl) * DMODEL + n0 + wn * 32 + tig * 2;
#pragma unroll
            for (int ni = 0; ni < 4; ni++) {
                int col = n0 + wn * 32 + ni * 8 + tig * 2;
                float2 st;
                st.x = acc[mi][ni][half * 2 + 0] + bias[col];
                st.y = acc[mi][ni][half * 2 + 1] + bias[col + 1];
                *(float2*)&Y[rbase + ni * 8] = st;
            }
        }
    }
}

// Merged Q/K/V projection: blockIdx.z selects the (X, W, b, Y) triple.
__global__ __launch_bounds__(256) void proj_mma3(
    const float* __restrict__ X0, const float* __restrict__ X1,
    const float* __restrict__ X2,
    const float* __restrict__ W0, const float* __restrict__ W1,
    const float* __restrict__ W2,
    const float* __restrict__ b0, const float* __restrict__ b1,
    const float* __restrict__ b2,
    float* __restrict__ Y0, float* __restrict__ Y1, float* __restrict__ Y2)
{
    extern __shared__ char smem[];
    const int z = blockIdx.z;
    const float* X = (z == 0) ? X0 : (z == 1) ? X1 : X2;
    const float* W = (z == 0) ? W0 : (z == 1) ? W1 : W2;
    const float* bias = (z == 0) ? b0 : (z == 1) ? b1 : b2;
    float* Y = (z == 0) ? Y0 : (z == 1) ? Y1 : Y2;
    proj_body(X, W, bias, Y, smem);
}

// Single projection (output layer)
__global__ __launch_bounds__(256) void proj_mma(
    const float* __restrict__ X, const float* __restrict__ W,
    const float* __restrict__ bias, float* __restrict__ Y)
{
    extern __shared__ char smem[];
    proj_body(X, W, bias, Y, smem);
}

// ---------------------------------------------------------------------------
// scores_mma (R12-proven body, + head-group offset bh0):
// E = exp(0.125 * Q K^T) via tf32 mma.sync. CTA 128x128, warp 64x32.
// Writes unnormalized exp to attn; deterministic rowsum partials to g_ps.
// grid = (NBLK, SEQ/128, HGRP); bh = bh0 + blockIdx.z.
// ---------------------------------------------------------------------------
__global__ __launch_bounds__(256) void scores_mma(
    const float* __restrict__ Q, const float* __restrict__ Km,
    float* __restrict__ attn, float* __restrict__ PS, int bh0)
{
    extern __shared__ char smem[];
    uint32_t* Qs = (uint32_t*)smem;               // stride 68 words
    uint32_t* Ks = (uint32_t*)(smem + 34816);
    __shared__ float psum[128][4];

    const int tid = threadIdx.x;
    const int wid = tid >> 5, lid = tid & 31;
    const int g = lid >> 2, tig = lid & 3;
    const int wm = wid >> 2, wn = wid & 3;        // 2 x 4 warp grid
    const int bh = bh0 + blockIdx.z;
    const int b = bh >> 3, h = bh & 7;
    const int m0 = blockIdx.y * 128, n0 = blockIdx.x * 128;

    const float* Qh = Q  + (size_t)b * SEQ * DMODEL + h * DH;
    const float* Kh = Km + (size_t)b * SEQ * DMODEL + h * DH;
    float* Sh = attn + (size_t)bh * SEQ * SEQ;

#pragma unroll
    for (int i = 0; i < 8; i++) {
        int idx = tid + i * 256;
        int r = idx >> 4, c4 = idx & 15;
        float4 q = *(const float4*)&Qh[(size_t)(m0 + r) * DMODEL + c4 * 4];
        q.x *= 0.125f; q.y *= 0.125f; q.z *= 0.125f; q.w *= 0.125f;
        *(uint4*)(Qs + r * 68 + c4 * 4) = tf32x4(q);
        float4 k = *(const float4*)&Kh[(size_t)(n0 + r) * DMODEL + c4 * 4];
        *(uint4*)(Ks + r * 68 + c4 * 4) = tf32x4(k);
    }
    __syncthreads();

    float acc[4][4][4] = {};
#pragma unroll
    for (int ks = 0; ks < 8; ks++) {
        const int k0 = ks * 8;
        uint32_t A[4][4], Bf[4][2];
#pragma unroll
        for (int mi = 0; mi < 4; mi++) {
            const uint32_t* p = Qs + (wm * 64 + mi * 16 + g) * 68 + k0 + tig;
            A[mi][0] = p[0];
            A[mi][1] = p[8 * 68];
            A[mi][2] = p[4];
            A[mi][3] = p[8 * 68 + 4];
        }
#pragma unroll
        for (int ni = 0; ni < 4; ni++) {
            const uint32_t* p = Ks + (wn * 32 + ni * 8 + g) * 68 + k0 + tig;
            Bf[ni][0] = p[0];
            Bf[ni][1] = p[4];
        }
#pragma unroll
        for (int mi = 0; mi < 4; mi++)
#pragma unroll
            for (int ni = 0; ni < 4; ni++)
                mma_tf32(acc[mi][ni], A[mi], Bf[ni]);
    }

#pragma unroll
    for (int mi = 0; mi < 4; mi++) {
#pragma unroll
        for (int half = 0; half < 2; half++) {
            int rl = wm * 64 + mi * 16 + g + half * 8;
            size_t rbase = (size_t)(m0 + rl) * SEQ + n0 + wn * 32 + tig * 2;
            float rsum = 0.f;
#pragma unroll
            for (int ni = 0; ni < 4; ni++) {
                float e0 = __expf(acc[mi][ni][half * 2 + 0]);
                float e1 = __expf(acc[mi][ni][half * 2 + 1]);
                rsum += e0 + e1;
                float2 st; st.x = e0; st.y = e1;
                *(float2*)&Sh[rbase + ni * 8] = st;
            }
            rsum += __shfl_xor_sync(0xffffffffu, rsum, 1);
            rsum += __shfl_xor_sync(0xffffffffu, rsum, 2);
            if (tig == 0) psum[rl][wn] = rsum;
        }
    }
    __syncthreads();
    if (tid < 128) {
        float s = psum[tid][0] + psum[tid][1] + psum[tid][2] + psum[tid][3];
        PS[(size_t)blockIdx.x * (BHTOT * SEQ) + (size_t)bh * SEQ + m0 + tid] = s;
    }
}

// ---------------------------------------------------------------------------
// pv_mma (RACE-FIXED): ctx = softmax(E) @ V. M=128, N=64, K=4096.
// 3-stage cp.async pipeline with TWO barriers per chunk. The trailing
// barrier is REQUIRED: at iteration kc the issue targets buffer (kc+2)%3
// == (kc-1)%3, the buffer laggard threads are still reading in their
// iteration kc-1 consume phase. Without a barrier between those reads and
// the write-issue, the async write can land mid-read (exposed in R15 by
// co-residency contention; hidden before only by cp.async latency).
// Trailing barrier guarantees all reads of a buffer complete before any
// thread reaches the issue that overwrites it.
// Prologue folds rowsum reduction; normalized attn writeback rides on the
// consume phase; accumulator scaled by inv[row] in epilogue.
// grid = (SEQ/128, HGRP); bh = bh0 + blockIdx.y.
// Dyn smem: inv 128f @0; 3 stages x (Es 128x36f + Vs 32x68f) = 81920 B.
// ---------------------------------------------------------------------------
__global__ __launch_bounds__(256) void pv_mma(
    float* __restrict__ attn, const float* __restrict__ V,
    const float* __restrict__ PS, float* __restrict__ C, int bh0)
{
    extern __shared__ char smem[];
    float* invs = (float*)smem;
    const int OE[3] = {512, 27648, 54784};
    const int OV[3] = {18944, 46080, 73216};

    const int tid = threadIdx.x;
    const int wid = tid >> 5, lid = tid & 31;
    const int g = lid >> 2, tig = lid & 3;
    const int wm = wid >> 1, wn = wid & 1;        // 4 x 2 warp grid
    const int bh = bh0 + blockIdx.y;
    const int b = bh >> 3, h = bh & 7;
    const int m0 = blockIdx.x * 128;

    float* Eh = attn + (size_t)bh * SEQ * SEQ;
    const float* Vh = V + (size_t)b * SEQ * DMODEL + h * DH;
    const uint32_t sbase = smem_u32(smem);

    // Folded rowsum reduction + reciprocal
    if (tid < 128) {
        float s = 0.f;
#pragma unroll
        for (int j = 0; j < NBLK; j++)
            s += PS[(size_t)j * (BHTOT * SEQ) + (size_t)bh * SEQ + m0 + tid];
        invs[tid] = 1.0f / s;
    }

    auto issue = [&](int kc, int buf) {
#pragma unroll
        for (int i = 0; i < 4; i++) {
            int idx = tid + i * 256;              // E: 128r x 8seg
            int r = idx >> 3, c = idx & 7;
            uint32_t dst = sbase + OE[buf] + r * 144 + c * 16;
            const float* src = &Eh[(size_t)(m0 + r) * SEQ + kc * 32 + c * 4];
            CP_ASYNC16(dst, src);
        }
#pragma unroll
        for (int i = 0; i < 2; i++) {
            int idx = tid + i * 256;              // V: 32r x 16seg
            int r = idx >> 4, c = idx & 15;
            uint32_t dst = sbase + OV[buf] + r * 272 + c * 16;
            const float* src = &Vh[(size_t)(kc * 32 + r) * DMODEL + c * 4];
            CP_ASYNC16(dst, src);
        }
    };

    float acc[2][4][4] = {};                      // [mi][ni][frag]

    const int NCHUNK = SEQ / 32;                  // 128
    issue(0, 0); CP_COMMIT();
    issue(1, 1); CP_COMMIT();
    __syncthreads();                              // invs visible

    for (int kc = 0; kc < NCHUNK; kc++) {
        const int buf = kc % 3;
        if (kc + 2 < NCHUNK) issue(kc + 2, (kc + 2) % 3);
        CP_COMMIT();
        CP_WAIT2();
        __syncthreads();                          // chunk kc resident, all threads

        const float* Es = (const float*)(smem + OE[buf]);   // stride 36 f
        const float* Vs = (const float*)(smem + OV[buf]);   // stride 68 f

        // Normalized attn writeback (independent of MMA below)
#pragma unroll
        for (int i = 0; i < 4; i++) {
            int idx = tid + i * 256;
            int r = idx >> 3, c = idx & 7;
            float4 v = *(const float4*)(smem + OE[buf] + r * 144 + c * 16);
            float iv = invs[r];
            float4 nv;
            nv.x = v.x * iv; nv.y = v.y * iv; nv.z = v.z * iv; nv.w = v.w * iv;
            *(float4*)&Eh[(size_t)(m0 + r) * SEQ + kc * 32 + c * 4] = nv;
        }

        // MMA over chunk (A = raw E as tf32, un-normalized)
#pragma unroll
        for (int ks = 0; ks < 4; ks++) {
            const int k0 = ks * 8;
            uint32_t A[2][4], Bf[4][2];
#pragma unroll
            for (int mi = 0; mi < 2; mi++) {
                const float* p = Es + (wm * 32 + mi * 16 + g) * 36 + k0 + tig;
                A[mi][0] = cvt_tf32(p[0]);
                A[mi][1] = cvt_tf32(p[8 * 36]);
                A[mi][2] = cvt_tf32(p[4]);
                A[mi][3] = cvt_tf32(p[8 * 36 + 4]);
            }
#pragma unroll
            for (int ni = 0; ni < 4; ni++) {
                int n = wn * 32 + ni * 8 + g;
                Bf[ni][0] = cvt_tf32(Vs[(k0 + tig) * 68 + n]);
                Bf[ni][1] = cvt_tf32(Vs[(k0 + tig + 4) * 68 + n]);
            }
#pragma unroll
            for (int mi = 0; mi < 2; mi++)
#pragma unroll
                for (int ni = 0; ni < 4; ni++)
                    mma_tf32(acc[mi][ni], A[mi], Bf[ni]);
        }
        __syncthreads();   // REQUIRED: all reads of this buffer done before
                           // any thread issues the overwrite (see header)
    }

    // Epilogue: scale by inv[row], write merged [B,N,512] layout at col h*64
#pragma unroll
    for (int mi = 0; mi < 2; mi++) {
#pragma unroll
        for (int half = 0; half < 2; half++) {
            int rl = wm * 32 + mi * 16 + g + half * 8;
            float iv = invs[rl];
            size_t orow = ((size_t)b * SEQ + m0 + rl) * DMODEL + h * DH
                        + wn * 32 + tig * 2;
#pragma unroll
            for (int ni = 0; ni < 4; ni++) {
                float2 st;
                st.x = acc[mi][ni][half * 2 + 0] * iv;
                st.y = acc[mi][ni][half * 2 + 1] * iv;
                *(float2*)&C[orow + ni * 8] = st;
            }
        }
    }
}

// ---------------------------------------------------------------------------
// Launch: per-head-group software pipeline across two streams.
//   stream0:  proj3 -> s(g0) -> s(g1) -> s(g2) -> s(g3) ----------\
//   streamB:            p(g0) ->  p(g1) ->  p(g2) ->  p(g3) -> join -> outproj
// scores (L1-bound) and pv (DRAM-bound) co-reside per SM
// (2x69632 + 81920 = 221184 B < 228 KB), overlapping their bottlenecks.
// Concurrent kernels share NO data: per-group bh slices of attn/PS are
// disjoint; Q/K/V read-only; C written only by pv, read by outproj after
// the event join.
// ---------------------------------------------------------------------------
extern "C" void kernel_launch(void* const* d_in, const int* in_sizes, int n_in,
                              void* d_out, int out_size)
{
    const float* query = (const float*)d_in[0];
    const float* key   = (const float*)d_in[1];
    const float* value = (const float*)d_in[2];
    const float* Wq = (const float*)d_in[3];
    const float* bq = (const float*)d_in[4];
    const float* Wk = (const float*)d_in[5];
    const float* bk = (const float*)d_in[6];
    const float* Wv = (const float*)d_in[7];
    const float* bv = (const float*)d_in[8];
    const float* Wo = (const float*)d_in[9];
    const float* bo = (const float*)d_in[10];

    float* out  = (float*)d_out;
    float* attn = out + (size_t)MTOT * DMODEL;

    float *Qd, *Kd, *Vd, *Cd, *PSd;
    cudaGetSymbolAddress((void**)&Qd,  g_Q);
    cudaGetSymbolAddress((void**)&Kd,  g_K);
    cudaGetSymbolAddress((void**)&Vd,  g_V);
    cudaGetSymbolAddress((void**)&Cd,  g_C);
    cudaGetSymbolAddress((void**)&PSd, g_ps);

    const int SMEM_TILES = 69632;     // 2 x 128 x 68 x 4 (proj + scores)
    const int SMEM_PV    = 81920;     // inv + 3 stages x 27136
    cudaFuncSetAttribute(proj_mma3,  cudaFuncAttributeMaxDynamicSharedMemorySize, SMEM_TILES);
    cudaFuncSetAttribute(proj_mma,   cudaFuncAttributeMaxDynamicSharedMemorySize, SMEM_TILES);
    cudaFuncSetAttribute(scores_mma, cudaFuncAttributeMaxDynamicSharedMemorySize, SMEM_TILES);
    cudaFuncSetAttribute(pv_mma,     cudaFuncAttributeMaxDynamicSharedMemorySize, SMEM_PV);

    cudaStream_t sB;
    cudaStreamCreateWithFlags(&sB, cudaStreamNonBlocking);

    // Q, K, V projections in ONE launch (768 CTAs) on the main stream
    dim3 proj3Grid(DMODEL / 128, MTOT / 128, 3);        // (4, 64, 3)
    proj_mma3<<<proj3Grid, 256, SMEM_TILES>>>(
        query, key, value, Wq, Wk, Wv, bq, bk, bv, Qd, Kd, Vd);

    dim3 scGrid(NBLK, SEQ / 128, HGRP);                 // (32, 32, 4)
    dim3 pvGrid(SEQ / 128, HGRP);                       // (32, 4)
    for (int grp = 0; grp < NGRP; grp++) {
        scores_mma<<<scGrid, 256, SMEM_TILES>>>(Qd, Kd, attn, PSd, grp * HGRP);
        cudaEvent_t evS;
        cudaEventCreateWithFlags(&evS, cudaEventDisableTiming);
        cudaEventRecord(evS, 0);
        cudaStreamWaitEvent(sB, evS, 0);
        pv_mma<<<pvGrid, 256, SMEM_PV, sB>>>(attn, Vd, PSd, Cd, grp * HGRP);
    }

    cudaEvent_t evJ;
    cudaEventCreateWithFlags(&evJ, cudaEventDisableTiming);
    cudaEventRecord(evJ, sB);
    cudaStreamWaitEvent(0, evJ, 0);

    dim3 projGrid(DMODEL / 128, MTOT / 128);            // (4, 64)
    proj_mma<<<projGrid, 256, SMEM_TILES>>>(Cd, Wo, bo, out);
}

// round 17
// speedup vs baseline: 1.1698x; 1.1698x over previous
#include <cuda_runtime.h>
#include <cstdint>
#include <cstddef>

// Problem constants
#define BB     2
#define SEQ    4096
#define DMODEL 512
#define NHEADS 8
#define DH     64
#define MTOT   (BB * SEQ)
#define BHTOT  (BB * NHEADS)
#define NBLK   (SEQ / 128)          // 32 n-blocks per row (scores tile = 128)

// Scratch device globals (no allocation allowed)
__device__ float g_Q[MTOT * DMODEL];
__device__ float g_K[MTOT * DMODEL];
__device__ float g_V[MTOT * DMODEL];
__device__ float g_C[MTOT * DMODEL];
__device__ float g_ps[NBLK * BHTOT * SEQ];   // rowsum partials [nblk][bh*SEQ+row]

// ---------------------------------------------------------------------------
// tf32 / async helpers (base ISA, no sm_103a-gated features)
// ---------------------------------------------------------------------------
__device__ __forceinline__ uint32_t cvt_tf32(float f) {
    uint32_t u;
    asm("cvt.rna.tf32.f32 %0, %1;" : "=r"(u) : "f"(f));
    return u;
}

__device__ __forceinline__ uint32_t smem_u32(const void* p) {
    uint32_t a;
    asm("{ .reg .u64 t; cvta.to.shared.u64 t, %1; cvt.u32.u64 %0, t; }"
        : "=r"(a) : "l"(p));
    return a;
}

#define CP_ASYNC16(dst_u32, src_ptr) \
    asm volatile("cp.async.cg.shared.global [%0], [%1], 16;" \
        :: "r"(dst_u32), "l"(src_ptr) : "memory")
#define CP_COMMIT() asm volatile("cp.async.commit_group;" ::: "memory")
#define CP_WAIT0()  asm volatile("cp.async.wait_group 0;" ::: "memory")
#define CP_WAIT1()  asm volatile("cp.async.wait_group 1;" ::: "memory")

// D = A(16x8, row) * B(8x8, col) + C, tf32 in / fp32 out. In-place C allowed.
__device__ __forceinline__ void mma_tf32(
    float d[4], const uint32_t a[4], const uint32_t b[2])
{
    asm volatile(
        "mma.sync.aligned.m16n8k8.row.col.f32.tf32.tf32.f32 "
        "{%0,%1,%2,%3}, {%4,%5,%6,%7}, {%8,%9}, {%0,%1,%2,%3};\n"
        : "+f"(d[0]), "+f"(d[1]), "+f"(d[2]), "+f"(d[3])
        : "r"(a[0]), "r"(a[1]), "r"(a[2]), "r"(a[3]),
          "r"(b[0]), "r"(b[1]));
}

// ---------------------------------------------------------------------------
// Core projection body: Y = X @ W^T + b. CTA 128x128, 8 warps 2x4,
// warp 64x32, K = 512 in 8 staged chunks.
// Staging via cp.async.cg (RAW floats, L1-bypassed); tf32 conversion at
// fragment-load time (each element converted exactly once).
// Dyn smem: Xs 128x68 f @0, Ws 128x68 f @34816 -> 69632 bytes.
// ---------------------------------------------------------------------------
__device__ __forceinline__ void proj_body(
    const float* __restrict__ X, const float* __restrict__ W,
    const float* __restrict__ bias, float* __restrict__ Y, char* smem)
{
    float* Xs = (float*)smem;                     // stride 68 floats
    float* Ws = (float*)(smem + 34816);
    const uint32_t sbase = smem_u32(smem);

    const int tid = threadIdx.x;
    const int wid = tid >> 5, lid = tid & 31;
    const int g = lid >> 2, tig = lid & 3;
    const int wm = wid >> 2, wn = wid & 3;        // 2 x 4 warp grid
    const int m0 = blockIdx.y * 128, n0 = blockIdx.x * 128;

    float acc[4][4][4] = {};                      // [mi][ni][frag]

    for (int kc = 0; kc < DMODEL / 64; kc++) {
        const int kb = kc * 64;
#pragma unroll
        for (int i = 0; i < 8; i++) {
            int idx = tid + i * 256;              // 0..2047
            int r = idx >> 4, c4 = idx & 15;      // 16 float4 per 64-col row
            CP_ASYNC16(sbase + r * 272 + c4 * 16,
                       &X[(size_t)(m0 + r) * DMODEL + kb + c4 * 4]);
            CP_ASYNC16(sbase + 34816 + r * 272 + c4 * 16,
                       &W[(size_t)(n0 + r) * DMODEL + kb + c4 * 4]);
        }
        CP_COMMIT();
        CP_WAIT0();
        __syncthreads();
#pragma unroll
        for (int ks = 0; ks < 8; ks++) {
            const int k0 = ks * 8;
            uint32_t A[4][4], Bf[4][2];
#pragma unroll
            for (int mi = 0; mi < 4; mi++) {
                const float* p = Xs + (wm * 64 + mi * 16 + g) * 68 + k0 + tig;
                A[mi][0] = cvt_tf32(p[0]);
                A[mi][1] = cvt_tf32(p[8 * 68]);
                A[mi][2] = cvt_tf32(p[4]);
                A[mi][3] = cvt_tf32(p[8 * 68 + 4]);
            }
#pragma unroll
            for (int ni = 0; ni < 4; ni++) {
                const float* p = Ws + (wn * 32 + ni * 8 + g) * 68 + k0 + tig;
                Bf[ni][0] = cvt_tf32(p[0]);
                Bf[ni][1] = cvt_tf32(p[4]);
            }
#pragma unroll
            for (int mi = 0; mi < 4; mi++)
#pragma unroll
                for (int ni = 0; ni < 4; ni++)
                    mma_tf32(acc[mi][ni], A[mi], Bf[ni]);
        }
        __syncthreads();
    }

    // Epilogue: bias add, float2 stores
#pragma unroll
    for (int mi = 0; mi < 4; mi++) {
#pragma unroll
        for (int half = 0; half < 2; half++) {
            int rl = wm * 64 + mi * 16 + g + half * 8;
            size_t rbase = (size_t)(m0 + rl) * DMODEL + n0 + wn * 32 + tig * 2;
#pragma unroll
            for (int ni = 0; ni < 4; ni++) {
                int col = n0 + wn * 32 + ni * 8 + tig * 2;
                float2 st;
                st.x = acc[mi][ni][half * 2 + 0] + bias[col];
                st.y = acc[mi][ni][half * 2 + 1] + bias[col + 1];
                *(float2*)&Y[rbase + ni * 8] = st;
            }
        }
    }
}

// Merged Q/K/V projection: blockIdx.z selects the (X, W, b, Y) triple.
__global__ __launch_bounds__(256) void proj_mma3(
    const float* __restrict__ X0, const float* __restrict__ X1,
    const float* __restrict__ X2,
    const float* __restrict__ W0, const float* __restrict__ W1,
    const float* __restrict__ W2,
    const float* __restrict__ b0, const float* __restrict__ b1,
    const float* __restrict__ b2,
    float* __restrict__ Y0, float* __restrict__ Y1, float* __restrict__ Y2)
{
    extern __shared__ char smem[];
    const int z = blockIdx.z;
    const float* X = (z == 0) ? X0 : (z == 1) ? X1 : X2;
    const float* W = (z == 0) ? W0 : (z == 1) ? W1 : W2;
    const float* bias = (z == 0) ? b0 : (z == 1) ? b1 : b2;
    float* Y = (z == 0) ? Y0 : (z == 1) ? Y1 : Y2;
    proj_body(X, W, bias, Y, smem);
}

// Single projection (output layer)
__global__ __launch_bounds__(256) void proj_mma(
    const float* __restrict__ X, const float* __restrict__ W,
    const float* __restrict__ bias, float* __restrict__ Y)
{
    extern __shared__ char smem[];
    proj_body(X, W, bias, Y, smem);
}

// ---------------------------------------------------------------------------
// scores_mma: E = exp(0.125 * Q K^T) via tf32 mma.sync. CTA 128x128,
// 8 warps 2x4, warp 64x32.
// Staging via cp.async.cg (RAW floats, L1-bypassed — removes the 64KB/CTA
// LDG pass from the L1-bound pipe); tf32 conversion at fragment-load time.
// Scale 0.125 folded into the exp argument (was Q pre-scale).
// Writes unnormalized exp to attn; deterministic rowsum partials to g_ps.
// Dyn smem: Qs 128x68 f @0, Ks 128x68 f @34816 -> 69632 bytes.
// ---------------------------------------------------------------------------
__global__ __launch_bounds__(256) void scores_mma(
    const float* __restrict__ Q, const float* __restrict__ Km,
    float* __restrict__ attn, float* __restrict__ PS)
{
    extern __shared__ char smem[];
    float* Qs = (float*)smem;                     // stride 68 floats
    float* Ks = (float*)(smem + 34816);
    __shared__ float psum[128][4];
    const uint32_t sbase = smem_u32(smem);

    const int tid = threadIdx.x;
    const int wid = tid >> 5, lid = tid & 31;
    const int g = lid >> 2, tig = lid & 3;
    const int wm = wid >> 2, wn = wid & 3;        // 2 x 4 warp grid
    const int bh = blockIdx.z;
    const int b = bh >> 3, h = bh & 7;
    const int m0 = blockIdx.y * 128, n0 = blockIdx.x * 128;

    const float* Qh = Q  + (size_t)b * SEQ * DMODEL + h * DH;
    const float* Kh = Km + (size_t)b * SEQ * DMODEL + h * DH;
    float* Sh = attn + (size_t)bh * SEQ * SEQ;

#pragma unroll
    for (int i = 0; i < 8; i++) {
        int idx = tid + i * 256;
        int r = idx >> 4, c4 = idx & 15;
        CP_ASYNC16(sbase + r * 272 + c4 * 16,
                   &Qh[(size_t)(m0 + r) * DMODEL + c4 * 4]);
        CP_ASYNC16(sbase + 34816 + r * 272 + c4 * 16,
                   &Kh[(size_t)(n0 + r) * DMODEL + c4 * 4]);
    }
    CP_COMMIT();
    CP_WAIT0();
    __syncthreads();

    float acc[4][4][4] = {};
#pragma unroll
    for (int ks = 0; ks < 8; ks++) {
        const int k0 = ks * 8;
        uint32_t A[4][4], Bf[4][2];
#pragma unroll
        for (int mi = 0; mi < 4; mi++) {
            const float* p = Qs + (wm * 64 + mi * 16 + g) * 68 + k0 + tig;
            A[mi][0] = cvt_tf32(p[0]);
            A[mi][1] = cvt_tf32(p[8 * 68]);
            A[mi][2] = cvt_tf32(p[4]);
            A[mi][3] = cvt_tf32(p[8 * 68 + 4]);
        }
#pragma unroll
        for (int ni = 0; ni < 4; ni++) {
            const float* p = Ks + (wn * 32 + ni * 8 + g) * 68 + k0 + tig;
            Bf[ni][0] = cvt_tf32(p[0]);
            Bf[ni][1] = cvt_tf32(p[4]);
        }
#pragma unroll
        for (int mi = 0; mi < 4; mi++)
#pragma unroll
            for (int ni = 0; ni < 4; ni++)
                mma_tf32(acc[mi][ni], A[mi], Bf[ni]);
    }

#pragma unroll
    for (int mi = 0; mi < 4; mi++) {
#pragma unroll
        for (int half = 0; half < 2; half++) {
            int rl = wm * 64 + mi * 16 + g + half * 8;
            size_t rbase = (size_t)(m0 + rl) * SEQ + n0 + wn * 32 + tig * 2;
            float rsum = 0.f;
#pragma unroll
            for (int ni = 0; ni < 4; ni++) {
                float e0 = __expf(acc[mi][ni][half * 2 + 0] * 0.125f);
                float e1 = __expf(acc[mi][ni][half * 2 + 1] * 0.125f);
                rsum += e0 + e1;
                float2 st; st.x = e0; st.y = e1;
                *(float2*)&Sh[rbase + ni * 8] = st;
            }
            rsum += __shfl_xor_sync(0xffffffffu, rsum, 1);
            rsum += __shfl_xor_sync(0xffffffffu, rsum, 2);
            if (tig == 0) psum[rl][wn] = rsum;
        }
    }
    __syncthreads();
    if (tid < 128) {
        float s = psum[tid][0] + psum[tid][1] + psum[tid][2] + psum[tid][3];
        PS[(size_t)blockIdx.x * (BHTOT * SEQ) + (size_t)bh * SEQ + m0 + tid] = s;
    }
}

// ---------------------------------------------------------------------------
// pv_mma: ctx = softmax(E) @ V. M=128, N=64, K=4096.
// 3-stage cp.async pipeline, ONE barrier per chunk, RACE-FREE by ordering:
//   wait_group 1  -> own chunk-kc groups landed
//   __syncthreads -> all threads: kc resident AND all reads of buffer
//                    (kc+2)%3 == (kc-1)%3 (done at iter kc-1) complete
//   issue(kc+2)   -> overwrite is ordered AFTER those reads
//   consume(kc)
// Per-address cp.async also completes (wait) before that thread's
// normalized STG overwrite (same idx mapping in issue and writeback).
// Prologue folds rowsum reduction; normalized attn writeback (__stcs,
// streaming) rides on the consume phase; accumulator scaled by inv[row].
// Dyn smem: inv 128f @0; 3 stages x (Es 128x36f + Vs 32x68f) = 81920 B.
// ---------------------------------------------------------------------------
__global__ __launch_bounds__(256) void pv_mma(
    float* __restrict__ attn, const float* __restrict__ V,
    const float* __restrict__ PS, float* __restrict__ C)
{
    extern __shared__ char smem[];
    float* invs = (float*)smem;
    const int OE[3] = {512, 27648, 54784};
    const int OV[3] = {18944, 46080, 73216};

    const int tid = threadIdx.x;
    const int wid = tid >> 5, lid = tid & 31;
    const int g = lid >> 2, tig = lid & 3;
    const int wm = wid >> 1, wn = wid & 1;        // 4 x 2 warp grid
    const int bh = blockIdx.y;
    const int b = bh >> 3, h = bh & 7;
    const int m0 = blockIdx.x * 128;

    float* Eh = attn + (size_t)bh * SEQ * SEQ;
    const float* Vh = V + (size_t)b * SEQ * DMODEL + h * DH;
    const uint32_t sbase = smem_u32(smem);

    // Folded rowsum reduction + reciprocal (visible after iter-0 barrier)
    if (tid < 128) {
        float s = 0.f;
#pragma unroll
        for (int j = 0; j < NBLK; j++)
            s += PS[(size_t)j * (BHTOT * SEQ) + (size_t)bh * SEQ + m0 + tid];
        invs[tid] = 1.0f / s;
    }

    auto issue = [&](int kc, int buf) {
#pragma unroll
        for (int i = 0; i < 4; i++) {
            int idx = tid + i * 256;              // E: 128r x 8seg
            int r = idx >> 3, c = idx & 7;
            uint32_t dst = sbase + OE[buf] + r * 144 + c * 16;
            const float* src = &Eh[(size_t)(m0 + r) * SEQ + kc * 32 + c * 4];
            CP_ASYNC16(dst, src);
        }
#pragma unroll
        for (int i = 0; i < 2; i++) {
            int idx = tid + i * 256;              // V: 32r x 16seg
            int r = idx >> 4, c = idx & 15;
            uint32_t dst = sbase + OV[buf] + r * 272 + c * 16;
            const float* src = &Vh[(size_t)(kc * 32 + r) * DMODEL + c * 4];
            CP_ASYNC16(dst, src);
        }
    };

    float acc[2][4][4] = {};                      // [mi][ni][frag]

    const int NCHUNK = SEQ / 32;                  // 128
    issue(0, 0); CP_COMMIT();
    issue(1, 1); CP_COMMIT();

    for (int kc = 0; kc < NCHUNK; kc++) {
        const int buf = kc % 3;
        CP_WAIT1();                               // own chunk-kc groups done
        __syncthreads();                          // see header: makes issue safe
        if (kc + 2 < NCHUNK) issue(kc + 2, (kc + 2) % 3);
        CP_COMMIT();                              // always commit (group count)

        const float* Es = (const float*)(smem + OE[buf]);   // stride 36 f
        const float* Vs = (const float*)(smem + OV[buf]);   // stride 68 f

        // Normalized attn writeback (streaming stores; independent of MMA)
#pragma unroll
        for (int i = 0; i < 4; i++) {
            int idx = tid + i * 256;
            int r = idx >> 3, c = idx & 7;
            float4 v = *(const float4*)(smem + OE[buf] + r * 144 + c * 16);
            float iv = invs[r];
            float4 nv;
            nv.x = v.x * iv; nv.y = v.y * iv; nv.z = v.z * iv; nv.w = v.w * iv;
            __stcs((float4*)&Eh[(size_t)(m0 + r) * SEQ + kc * 32 + c * 4], nv);
        }

        // MMA over chunk (A = raw E as tf32, un-normalized)
#pragma unroll
        for (int ks = 0; ks < 4; ks++) {
            const int k0 = ks * 8;
            uint32_t A[2][4], Bf[4][2];
#pragma unroll
            for (int mi = 0; mi < 2; mi++) {
                const float* p = Es + (wm * 32 + mi * 16 + g) * 36 + k0 + tig;
                A[mi][0] = cvt_tf32(p[0]);
                A[mi][1] = cvt_tf32(p[8 * 36]);
                A[mi][2] = cvt_tf32(p[4]);
                A[mi][3] = cvt_tf32(p[8 * 36 + 4]);
            }
#pragma unroll
            for (int ni = 0; ni < 4; ni++) {
                int n = wn * 32 + ni * 8 + g;
                Bf[ni][0] = cvt_tf32(Vs[(k0 + tig) * 68 + n]);
                Bf[ni][1] = cvt_tf32(Vs[(k0 + tig + 4) * 68 + n]);
            }
#pragma unroll
            for (int mi = 0; mi < 2; mi++)
#pragma unroll
                for (int ni = 0; ni < 4; ni++)
                    mma_tf32(acc[mi][ni], A[mi], Bf[ni]);
        }
    }

    // Epilogue: scale by inv[row], write merged [B,N,512] layout at col h*64
#pragma unroll
    for (int mi = 0; mi < 2; mi++) {
#pragma unroll
        for (int half = 0; half < 2; half++) {
            int rl = wm * 32 + mi * 16 + g + half * 8;
            float iv = invs[rl];
            size_t orow = ((size_t)b * SEQ + m0 + rl) * DMODEL + h * DH
                        + wn * 32 + tig * 2;
#pragma unroll
            for (int ni = 0; ni < 4; ni++) {
                float2 st;
                st.x = acc[mi][ni][half * 2 + 0] * iv;
                st.y = acc[mi][ni][half * 2 + 1] * iv;
                *(float2*)&C[orow + ni * 8] = st;
            }
        }
    }
}

// ---------------------------------------------------------------------------
// Launch: single stream (two-stream overlap abandoned — R15/R16 showed
// contention loss exceeds overlap gain).
// ---------------------------------------------------------------------------
extern "C" void kernel_launch(void* const* d_in, const int* in_sizes, int n_in,
                              void* d_out, int out_size)
{
    const float* query = (const float*)d_in[0];
    const float* key   = (const float*)d_in[1];
    const float* value = (const float*)d_in[2];
    const float* Wq = (const float*)d_in[3];
    const float* bq = (const float*)d_in[4];
    const float* Wk = (const float*)d_in[5];
    const float* bk = (const float*)d_in[6];
    const float* Wv = (const float*)d_in[7];
    const float* bv = (const float*)d_in[8];
    const float* Wo = (const float*)d_in[9];
    const float* bo = (const float*)d_in[10];

    float* out  = (float*)d_out;
    float* attn = out + (size_t)MTOT * DMODEL;

    float *Qd, *Kd, *Vd, *Cd, *PSd;
    cudaGetSymbolAddress((void**)&Qd,  g_Q);
    cudaGetSymbolAddress((void**)&Kd,  g_K);
    cudaGetSymbolAddress((void**)&Vd,  g_V);
    cudaGetSymbolAddress((void**)&Cd,  g_C);
    cudaGetSymbolAddress((void**)&PSd, g_ps);

    const int SMEM_TILES = 69632;     // 2 x 128 x 68 x 4 (proj + scores)
    const int SMEM_PV    = 81920;     // inv + 3 stages x 27136
    cudaFuncSetAttribute(proj_mma3,  cudaFuncAttributeMaxDynamicSharedMemorySize, SMEM_TILES);
    cudaFuncSetAttribute(proj_mma,   cudaFuncAttributeMaxDynamicSharedMemorySize, SMEM_TILES);
    cudaFuncSetAttribute(scores_mma, cudaFuncAttributeMaxDynamicSharedMemorySize, SMEM_TILES);
    cudaFuncSetAttribute(pv_mma,     cudaFuncAttributeMaxDynamicSharedMemorySize, SMEM_PV);

    // Q, K, V projections in ONE launch (768 CTAs)
    dim3 proj3Grid(DMODEL / 128, MTOT / 128, 3);        // (4, 64, 3)
    proj_mma3<<<proj3Grid, 256, SMEM_TILES>>>(
        query, key, value, Wq, Wk, Wv, bq, bk, bv, Qd, Kd, Vd);

    dim3 scGrid(NBLK, SEQ / 128, BHTOT);                // (32, 32, 16)
    scores_mma<<<scGrid, 256, SMEM_TILES>>>(Qd, Kd, attn, PSd);

    dim3 pvGrid(SEQ / 128, BHTOT);                      // (32, 16)
    pv_mma<<<pvGrid, 256, SMEM_PV>>>(attn, Vd, PSd, Cd);

    dim3 projGrid(DMODEL / 128, MTOT / 128);            // (4, 64)
    proj_mma<<<projGrid, 256, SMEM_TILES>>>(Cd, Wo, bo, out);
}